// round 15
// baseline (speedup 1.0000x reference)
#include <cuda_runtime.h>
#include <cstdint>
#include <cfloat>

// Problem constants (fixed by dataset)
#define NN    2048
#define TT    128
#define KSEL  20
#define MAXA  20
#define LRC   0.01f
#define EPSC  1e-8f
#define NW32  (NN/32)
#define PROWS 8            // sigma rows per panel block
#define PSTR  2056         // padded panel row stride (floats)
#define GRIDN 256          // 256 blocks = panels; residency 2/SM guaranteed
#define NTHR  256

// ---------------- device scratch ---------------------------------------------
__device__ static float    g_B[(TT - 1) * NN];
__device__ static int16_t  g_act_idx[TT * MAXA];
__device__ static int      g_act_cnt[TT];
__device__ static int      g_act_cntfull[TT];
__device__ static unsigned g_act_mask[TT * NW32];
__device__ static unsigned g_arrive;     // cumulative ticket
__device__ static unsigned g_release;    // monotonic generation

// grid-wide barrier: cumulative tickets, monotonic release (graph-replay-safe)
__device__ __forceinline__ void gsync() {
    __syncthreads();
    if (threadIdx.x == 0) {
        __threadfence();
        const unsigned tk = atomicAdd(&g_arrive, 1u);
        const unsigned target = tk / GRIDN + 1u;
        if ((tk % GRIDN) == GRIDN - 1u) {
            atomicExch(&g_release, target);
        } else {
            unsigned r;
            for (;;) {
                asm volatile("ld.volatile.global.u32 %0, [%1];"
                             : "=r"(r) : "l"(&g_release));
                if (r >= target) break;
                __nanosleep(64);
            }
        }
        __threadfence();
    }
    __syncthreads();
}

// dynamic smem layout (bytes):
// phaseA: panel 65792 @0 | hist 8192 @65792 | idx 5120 @73984 | acnt 128 @79104
//         misc 256 @79232 (wsum 32, cand 128, scalars) | mask 256 @79488
// phaseC overlay (inside old panel region): cw 40960 @0 | pos 2048 @43008 | red 128 @45056
#define OFF_HIST  65792
#define OFF_IDX   73984
#define OFF_ACNT  79104
#define OFF_MISC  79232
#define OFF_MASK  79488
#define OFF_POS   43008
#define OFF_RED   45056
#define SMEM_SZ   79872

__global__ void __launch_bounds__(NTHR, 2)
k_all(const int* __restrict__ tokens, const float* __restrict__ proj,
      const float* __restrict__ S, const int* __restrict__ plast,
      float* __restrict__ out) {
    extern __shared__ __align__(16) char s_raw[];
    const int bx   = blockIdx.x;
    const int tid  = threadIdx.x;
    const int lane = tid & 31;
    const int wid  = tid >> 5;

    float*   panel = reinterpret_cast<float*>(s_raw);
    int16_t* idx   = reinterpret_cast<int16_t*>(s_raw + OFF_IDX);
    uint8_t* acnt  = reinterpret_cast<uint8_t*>(s_raw + OFF_ACNT);

    const int pl = *plast;

    // ===== phase A1: stage this block's 8-row sigma panel (overlaps topk) ====
    {
        const int i0 = bx * PROWS;
        #pragma unroll
        for (int k = 0; k < 16; k++) {
            const int e   = k * NTHR + tid;    // float4 index within panel
            const int row = e >> 9;            // 512 float4 per row
            const int c4  = e & 511;
            const float4 sv = *reinterpret_cast<const float4*>(
                S + (size_t)(i0 + row) * NN + c4 * 4);
            *reinterpret_cast<float4*>(panel + row * PSTR + c4 * 4) = sv;
        }
    }

    // ===== phase A2: top-K for token t = bx (blocks 0..127) ===================
    if (bx < TT) {
        const int t = bx;
        unsigned* hist    = reinterpret_cast<unsigned*>(s_raw + OFF_HIST);
        unsigned* wsum    = reinterpret_cast<unsigned*>(s_raw + OFF_MISC);
        unsigned* cand    = reinterpret_cast<unsigned*>(s_raw + OFF_MISC + 32);
        unsigned* sprefix = reinterpret_cast<unsigned*>(s_raw + OFF_MISC + 160);
        unsigned* sthr    = reinterpret_cast<unsigned*>(s_raw + OFF_MISC + 164);
        int*      skk2    = reinterpret_cast<int*>(s_raw + OFF_MISC + 168);
        int*      sbc     = reinterpret_cast<int*>(s_raw + OFF_MISC + 172);
        int*      snc     = reinterpret_cast<int*>(s_raw + OFF_MISC + 176);
        int*      scnt    = reinterpret_cast<int*>(s_raw + OFF_MISC + 180);
        unsigned* smask   = reinterpret_cast<unsigned*>(s_raw + OFF_MASK);

        const float4* rp = reinterpret_cast<const float4*>(
            proj + (size_t)tokens[t] * NN);
        const float4 a = rp[tid * 2], b = rp[tid * 2 + 1];
        const float vv[8] = {a.x, a.y, a.z, a.w, b.x, b.y, b.z, b.w};
        unsigned key[8];
        #pragma unroll
        for (int m = 0; m < 8; m++) {
            const unsigned u = __float_as_uint(vv[m]);
            key[m] = (u >> 31) ? ~u : (u | 0x80000000u);
        }

        unsigned prefix = 0u, thr = 0u, Tlev = NN;
        int kkcur = KSEL;

        #pragma unroll
        for (int level = 0; level < 3; level++) {
            const int      SH = (level == 0) ? 21 : ((level == 1) ? 10 : 0);
            const int      WB = (level == 2) ? 10 : 11;
            const unsigned WM = (level == 2) ? 0x3FFu : 0x7FFu;

            reinterpret_cast<uint4*>(hist)[tid]       = make_uint4(0, 0, 0, 0);
            reinterpret_cast<uint4*>(hist)[tid + 256] = make_uint4(0, 0, 0, 0);
            __syncthreads();

            #pragma unroll
            for (int m = 0; m < 8; m++) {
                const bool part =
                    (level == 0) || ((key[m] >> (SH + WB)) == prefix);
                const unsigned bin = part ? ((key[m] >> SH) & WM) : 0xFFFFu;
                const unsigned mk  = __match_any_sync(0xFFFFFFFFu, bin);
                if (part && lane == (__ffs(mk) - 1))
                    atomicAdd(&hist[bin], (unsigned)__popc(mk));
            }
            __syncthreads();

            // block scan of 2048 bins, thread owns bins [tid*8, tid*8+8)
            const uint4 h0 = reinterpret_cast<const uint4*>(hist)[tid * 2];
            const uint4 h1 = reinterpret_cast<const uint4*>(hist)[tid * 2 + 1];
            const unsigned hv[8] = {h0.x, h0.y, h0.z, h0.w,
                                    h1.x, h1.y, h1.z, h1.w};
            unsigned lsum = 0;
            #pragma unroll
            for (int q = 0; q < 8; q++) lsum += hv[q];
            unsigned incl = lsum;
            #pragma unroll
            for (int o = 1; o < 32; o <<= 1) {
                const unsigned u = __shfl_up_sync(0xFFFFFFFFu, incl, o);
                if (lane >= o) incl += u;
            }
            if (lane == 31) wsum[wid] = incl;
            if (tid == 0) *snc = 0;
            __syncthreads();
            unsigned woff = 0u;
            for (int q = 0; q < wid; q++) woff += wsum[q];
            unsigned e = woff + incl - lsum;
            const unsigned target = Tlev - (unsigned)kkcur;
            #pragma unroll
            for (int c = 0; c < 8; c++) {
                const unsigned hb = hv[c];
                if (hb && e <= target && target < e + hb) {
                    *sprefix = (unsigned)(tid * 8 + c);
                    *skk2    = kkcur - (int)(Tlev - e - hb);
                    *sbc     = (int)hb;
                }
                e += hb;
            }
            __syncthreads();

            prefix = (prefix << WB) | *sprefix;
            kkcur  = *skk2;
            const int bc = *sbc;
            Tlev = (unsigned)bc;

            if (level == 2) { thr = prefix; break; }
            if (bc <= 32) {
                #pragma unroll
                for (int m = 0; m < 8; m++) {
                    if ((key[m] >> SH) == prefix) {
                        const int p = atomicAdd(snc, 1);
                        cand[p] = key[m];
                    }
                }
                __syncthreads();
                if (tid < 32) {
                    const int nc = *snc;
                    const unsigned c = (lane < nc) ? cand[lane] : 0u;
                    int g = 0, eq = 0;
                    for (int j = 0; j < nc; j++) {
                        const unsigned v = cand[j];
                        g  += (v > c);
                        eq += (v == c);
                    }
                    if (lane < nc && g < kkcur && kkcur <= g + eq) *sthr = c;
                }
                __syncthreads();
                thr = *sthr;
                break;
            }
        }

        if (tid < NW32) smask[tid] = 0u;
        if (tid == 0)   *scnt = 0;
        __syncthreads();
        #pragma unroll
        for (int m = 0; m < 8; m++) {
            if (key[m] >= thr) {
                const int i = tid * 8 + m;
                atomicOr(&smask[i >> 5], 1u << (i & 31));
                const int p = atomicAdd(scnt, 1);
                if (p < MAXA) g_act_idx[t * MAXA + p] = (int16_t)i;
            }
        }
        __syncthreads();
        const int cnt = *scnt;
        const int cc  = (cnt < MAXA) ? cnt : MAXA;
        if (tid >= cc && tid < MAXA) g_act_idx[t * MAXA + tid] = 0;
        if (tid < NW32) g_act_mask[t * NW32 + tid] = smask[tid];
        if (tid == 0) { g_act_cntfull[t] = cnt; g_act_cnt[t] = cc; }
    }

    gsync();

    // ===== phase B: panel sums -> g_B =========================================
    for (int x = tid; x < TT * MAXA / 2; x += NTHR)
        reinterpret_cast<int*>(idx)[x] = reinterpret_cast<const int*>(g_act_idx)[x];
    if (tid < TT) acnt[tid] = (uint8_t)g_act_cnt[tid];
    __syncthreads();

    for (int p = tid; p < (TT - 1) * PROWS; p += NTHR) {
        const int t  = p >> 3;
        const int il = p & 7;
        const int cnt = (int)acnt[t];
        const float* prow = panel + il * PSTR;
        float sum = 0.f;
        #pragma unroll
        for (int m = 0; m < MAXA; m++) {
            const float v = prow[(int)idx[t * MAXA + m]];
            if (m < cnt) sum += v;
        }
        g_B[t * NN + bx * PROWS + il] = sum;
    }

    gsync();

    // ===== phase C: tension for t = bx (blocks 0..126) ========================
    if (bx < TT - 1) {
        const int t  = bx;
        const int i0 = tid * 8;
        unsigned* cw  = reinterpret_cast<unsigned*>(s_raw);          // overlay
        uint8_t*  pos = reinterpret_cast<uint8_t*>(s_raw + OFF_POS);
        float*    red = reinterpret_cast<float*>(s_raw + OFF_RED);

        if (pl) {
            #pragma unroll
            for (int q = 0; q < 10; q++)
                reinterpret_cast<uint4*>(cw)[q * NTHR + tid] = make_uint4(0, 0, 0, 0);
            reinterpret_cast<unsigned*>(pos)[tid]       = 0xFFFFFFFFu;
            reinterpret_cast<unsigned*>(pos)[tid + 256] = 0xFFFFFFFFu;
        }
        __syncthreads();
        if (pl && tid < (int)acnt[t]) pos[(int)idx[t * MAXA + tid]] = (uint8_t)tid;
        __syncthreads();

        const float4 a4 = *reinterpret_cast<const float4*>(g_B + t * NN + i0);
        const float4 b4 = *reinterpret_cast<const float4*>(g_B + t * NN + i0 + 4);
        float p[8] = {a4.x, a4.y, a4.z, a4.w, b4.x, b4.y, b4.z, b4.w};

        if (pl) {
            // inline match scan + count expansion
            for (int wk = tid; wk < t * 32; wk += NTHR) {
                const int s = wk >> 5;
                const int m = wk & 31;
                if (m < (int)acnt[s]) {
                    const int j  = (int)idx[s * MAXA + m];
                    const int js = pos[j];
                    if (js != 0xFF) {
                        const int c2 = (int)acnt[s + 1];
                        const int b2 = (s + 1) * MAXA;
                        for (int mm = 0; mm < c2; mm++) {
                            const unsigned i = (unsigned)(int)idx[b2 + mm];
                            const unsigned off = (unsigned)js * NN + i;
                            atomicAdd(&cw[off >> 2], 1u << ((off & 3u) * 8u));
                        }
                    }
                }
            }
            __syncthreads();

            #pragma unroll
            for (int js = 0; js < MAXA; js++) {
                const unsigned w0 = cw[js * (NN / 4) + tid * 2];
                const unsigned w1 = cw[js * (NN / 4) + tid * 2 + 1];
                if (w0 | w1) {
                    const int j = (int)idx[t * MAXA + js];
                    #pragma unroll
                    for (int c = 0; c < 4; c++) {
                        const unsigned cc = (w0 >> (c * 8)) & 0xFFu;
                        if (cc) {
                            const float v = S[(size_t)(i0 + c) * NN + j];
                            p[c] += fminf(v + LRC * (float)cc, 1.0f) - v;
                        }
                    }
                    #pragma unroll
                    for (int c = 0; c < 4; c++) {
                        const unsigned cc = (w1 >> (c * 8)) & 0xFFu;
                        if (cc) {
                            const float v = S[(size_t)(i0 + 4 + c) * NN + j];
                            p[4 + c] += fminf(v + LRC * (float)cc, 1.0f) - v;
                        }
                    }
                }
            }
        }

        const unsigned mword = g_act_mask[(t + 1) * NW32 + (i0 >> 5)];
        const unsigned mb = (mword >> (i0 & 31)) & 0xFFu;
        float pn2 = 0.f, dt = 0.f;
        #pragma unroll
        for (int c = 0; c < 8; c++) {
            pn2 += p[c] * p[c];
            if ((mb >> c) & 1u) dt += p[c];
        }
        #pragma unroll
        for (int o = 16; o; o >>= 1) {
            pn2 += __shfl_xor_sync(0xFFFFFFFFu, pn2, o);
            dt  += __shfl_xor_sync(0xFFFFFFFFu, dt, o);
        }
        __syncthreads();
        if (lane == 0) { red[2 * wid] = pn2; red[2 * wid + 1] = dt; }
        __syncthreads();
        if (tid == 0) {
            float P2 = 0.f, D = 0.f;
            #pragma unroll
            for (int r = 0; r < 8; r++) { P2 += red[2 * r]; D += red[2 * r + 1]; }
            const float pn = sqrtf(P2);
            float tension;
            if (pl) {
                const float overlap = D / (pn * sqrtf((float)KSEL) + EPSC);
                tension = (pn > 0.0f) ? (1.0f - overlap) : 1.0f;
            } else {
                const float xn = sqrtf((float)g_act_cntfull[t + 1]);
                tension = 1.0f - D / (pn * xn + EPSC);
            }
            out[t] = tension;
        }
    }
}

// ---------------- launch ------------------------------------------------------
extern "C" void kernel_launch(void* const* d_in, const int* in_sizes, int n_in,
                              void* d_out, int out_size) {
    const int*   tokens = (const int*)d_in[0];
    const float* proj   = (const float*)d_in[1];
    const float* sigma  = (const float*)d_in[2];
    const int*   plast  = (const int*)d_in[3];
    float*       out    = (float*)d_out;

    cudaFuncSetAttribute(k_all, cudaFuncAttributeMaxDynamicSharedMemorySize,
                         SMEM_SZ);
    k_all<<<GRIDN, NTHR, SMEM_SZ>>>(tokens, proj, sigma, plast, out);
}

// round 16
// speedup vs baseline: 1.2424x; 1.2424x over previous
#include <cuda_runtime.h>
#include <cstdint>
#include <cfloat>

// Problem constants (fixed by dataset)
#define NN    2048
#define TT    128
#define KSEL  20
#define MAXA  20
#define LRC   0.01f
#define EPSC  1e-8f
#define NW32  (NN/32)
#define MCAP  2560
#define PROWS 8            // sigma rows per panel block
#define NPAN  (NN/PROWS)   // 256 panel blocks
#define PSTR  2056         // padded panel row stride (floats)

// ---------------- device scratch ---------------------------------------------
__device__ static float    g_B[(TT - 1) * NN];
__device__ static int16_t  g_act_idx[TT * MAXA];
__device__ static int      g_act_cnt[TT];
__device__ static int      g_act_cntfull[TT];
__device__ static unsigned g_act_mask[TT * NW32];
__device__ static unsigned g_match[(TT - 1) * MCAP];   // (js | s1<<8 | c2<<16)
__device__ static int      g_match_cnt[TT - 1];

// ========= K1: top-K, one block/token, 1-pass 2048-bin radix + resolve =======
__global__ void __launch_bounds__(512)
k_topk(const int* __restrict__ tokens, const float* __restrict__ proj) {
    const int t    = blockIdx.x;
    const int tid  = threadIdx.x;
    const int lane = tid & 31;
    const int wid  = tid >> 5;

    __shared__ unsigned hist[2048];     // 8 KB
    __shared__ unsigned wsum[16];
    __shared__ unsigned cand[32];
    __shared__ unsigned smask[NW32];
    __shared__ unsigned s_bin, s_thr;
    __shared__ int      s_kk2, s_bc, s_nc, s_cnt;

    const float4 a = *reinterpret_cast<const float4*>(
        proj + (size_t)tokens[t] * NN + tid * 4);
    const float vv[4] = {a.x, a.y, a.z, a.w};
    unsigned key[4];
    #pragma unroll
    for (int m = 0; m < 4; m++) {
        const unsigned u = __float_as_uint(vv[m]);
        key[m] = (u >> 31) ? ~u : (u | 0x80000000u);   // monotone map
    }

    unsigned prefix = 0u, thr = 0u, Tlev = NN;
    int kkcur = KSEL;

    #pragma unroll
    for (int level = 0; level < 3; level++) {
        const int      SH = (level == 0) ? 21 : ((level == 1) ? 10 : 0);
        const int      WB = (level == 2) ? 10 : 11;
        const unsigned WM = (level == 2) ? 0x3FFu : 0x7FFu;

        reinterpret_cast<uint4*>(hist)[tid] = make_uint4(0u, 0u, 0u, 0u);
        __syncthreads();

        #pragma unroll
        for (int m = 0; m < 4; m++) {
            const bool part =
                (level == 0) || ((key[m] >> (SH + WB)) == prefix);
            const unsigned bin = part ? ((key[m] >> SH) & WM) : 0xFFFFu;
            const unsigned mk  = __match_any_sync(0xFFFFFFFFu, bin);
            if (part && lane == (__ffs(mk) - 1))
                atomicAdd(&hist[bin], (unsigned)__popc(mk));
        }
        __syncthreads();

        // block scan of 2048 bins (ascending), locate boundary bin
        const uint4 h4 = reinterpret_cast<const uint4*>(hist)[tid];
        const unsigned hv[4] = {h4.x, h4.y, h4.z, h4.w};
        const unsigned lsum = hv[0] + hv[1] + hv[2] + hv[3];
        unsigned incl = lsum;
        #pragma unroll
        for (int o = 1; o < 32; o <<= 1) {
            const unsigned u = __shfl_up_sync(0xFFFFFFFFu, incl, o);
            if (lane >= o) incl += u;
        }
        if (lane == 31) wsum[wid] = incl;
        if (tid == 0) s_nc = 0;
        __syncthreads();
        unsigned woff = 0u;
        for (int q = 0; q < wid; q++) woff += wsum[q];
        unsigned e = woff + incl - lsum;           // exclusive prefix of bin 4tid
        const unsigned target = Tlev - (unsigned)kkcur;
        #pragma unroll
        for (int c = 0; c < 4; c++) {
            const unsigned hb = hv[c];
            if (hb && e <= target && target < e + hb) {
                s_bin = (unsigned)(tid * 4 + c);
                s_kk2 = kkcur - (int)(Tlev - e - hb);
                s_bc  = (int)hb;
            }
            e += hb;
        }
        __syncthreads();

        prefix = (prefix << WB) | s_bin;
        kkcur  = s_kk2;
        const int bc = s_bc;
        Tlev = (unsigned)bc;

        if (level == 2) { thr = prefix; break; }   // 32 bits exhausted: exact
        if (bc <= 32) {
            #pragma unroll
            for (int m = 0; m < 4; m++) {
                if ((key[m] >> SH) == prefix) {
                    const int p = atomicAdd(&s_nc, 1);
                    cand[p] = key[m];              // p < bc <= 32
                }
            }
            __syncthreads();
            if (tid < 32) {
                const int nc = s_nc;
                const unsigned c = (lane < nc) ? cand[lane] : 0u;
                int g = 0, eq = 0;
                for (int j = 0; j < nc; j++) {
                    const unsigned v = cand[j];
                    g  += (v > c);
                    eq += (v == c);
                }
                if (lane < nc && g < kkcur && kkcur <= g + eq) s_thr = c;
            }
            __syncthreads();
            thr = s_thr;
            break;
        }
    }

    // build mask + index list: key >= thr
    if (tid < NW32) smask[tid] = 0u;
    if (tid == 0)   s_cnt = 0;
    __syncthreads();
    #pragma unroll
    for (int m = 0; m < 4; m++) {
        if (key[m] >= thr) {
            const int i = tid * 4 + m;
            atomicOr(&smask[i >> 5], 1u << (i & 31));
            const int p = atomicAdd(&s_cnt, 1);
            if (p < MAXA) g_act_idx[t * MAXA + p] = (int16_t)i;
        }
    }
    __syncthreads();
    const int cnt = s_cnt;
    const int cc  = (cnt < MAXA) ? cnt : MAXA;
    if (tid >= cc && tid < MAXA) g_act_idx[t * MAXA + tid] = 0;   // pad for unroll
    if (tid < NW32) g_act_mask[t * NW32 + tid] = smask[tid];
    if (tid == 0) { g_act_cntfull[t] = cnt; g_act_cnt[t] = cc; }
}

// ====== K2: blocks 0..255 = 8-row panel sums; blocks 256..382 = match lists ==
__global__ void __launch_bounds__(512)
k_mid(const float* __restrict__ S, const int* __restrict__ plast) {
    const int bx  = blockIdx.x;
    const int tid = threadIdx.x;
    __shared__ __align__(16) char s_raw[71044];
    // panel 8*PSTR*4 = 65792 @0 | idx 5120 @65792 | acnt 128 @70912
    // match blocks overlay: pos 2048 @0 | cntp @2048
    float*   panel = reinterpret_cast<float*>(s_raw);
    int16_t* idx   = reinterpret_cast<int16_t*>(s_raw + 65792);
    uint8_t* acnt  = reinterpret_cast<uint8_t*>(s_raw + 70912);
    uint8_t* pos   = reinterpret_cast<uint8_t*>(s_raw);
    int*     cntp  = reinterpret_cast<int*>(s_raw + 2048);

    for (int x = tid; x < TT * MAXA / 2; x += 512)
        reinterpret_cast<int*>(idx)[x] = reinterpret_cast<const int*>(g_act_idx)[x];
    if (tid < TT) acnt[tid] = (uint8_t)g_act_cnt[tid];

    if (bx < NPAN) {
        // ---- one block per 8-row sigma panel ----
        const int i0 = bx * PROWS;
        #pragma unroll
        for (int k = 0; k < 8; k++) {
            const int e   = k * 512 + tid;     // float4 index within panel
            const int row = e >> 9;            // 512 float4 per row
            const int c4  = e & 511;
            const float4 sv = *reinterpret_cast<const float4*>(
                S + (size_t)(i0 + row) * NN + c4 * 4);
            *reinterpret_cast<float4*>(panel + row * PSTR + c4 * 4) = sv;
        }
        __syncthreads();

        #pragma unroll
        for (int p = 0; p < 2; p++) {
            const int w2 = p * 512 + tid;
            if (w2 < (TT - 1) * PROWS) {
                const int my_t  = w2 >> 3;
                const int my_il = w2 & 7;
                const int cnt   = (int)acnt[my_t];
                const float* prow = panel + my_il * PSTR;
                float sum = 0.f;
                #pragma unroll
                for (int m = 0; m < MAXA; m++) {
                    const float val = prow[(int)idx[my_t * MAXA + m]];
                    if (m < cnt) sum += val;
                }
                g_B[my_t * NN + i0 + my_il] = sum;
            }
        }
        return;
    }

    // ---- match list for t = bx - NPAN (pos overlays unused panel space) ----
    const int t = bx - NPAN;
    if (!*plast) { if (tid == 0) g_match_cnt[t] = 0; return; }
    if (tid < NN / 4) reinterpret_cast<unsigned*>(pos)[tid] = 0xFFFFFFFFu;
    if (tid == 0) *cntp = 0;
    __syncthreads();
    if (tid < (int)acnt[t]) pos[(int)idx[t * MAXA + tid]] = (uint8_t)tid;
    __syncthreads();
    for (int wk = tid; wk < t * 32; wk += 512) {
        const int s = wk >> 5;
        const int m = wk & 31;
        if (m < (int)acnt[s]) {
            const int j  = (int)idx[s * MAXA + m];
            const int js = pos[j];
            if (js != 0xFF) {
                const int p = atomicAdd(cntp, 1);
                g_match[t * MCAP + p] =
                    (unsigned)js | ((unsigned)(s + 1) << 8) |
                    ((unsigned)acnt[s + 1] << 16);
            }
        }
    }
    __syncthreads();
    if (tid == 0) g_match_cnt[t] = *cntp;
}

// ================= K3: tension, one block per t (full row, no combine) =======
__global__ void __launch_bounds__(512)
k_tension(const float* __restrict__ S, const int* __restrict__ plast,
          float* __restrict__ out) {
    const int t    = blockIdx.x;
    const int tid  = threadIdx.x;
    const int lane = tid & 31;
    const int w    = tid >> 5;
    const int i0   = tid * 4;

    __shared__ __align__(16) char s_raw[46336];
    // cw 40960 @0 | idx 5120 @40960 | red 128 @46080
    unsigned* cw  = reinterpret_cast<unsigned*>(s_raw);
    int16_t*  idx = reinterpret_cast<int16_t*>(s_raw + 40960);
    float*    red = reinterpret_cast<float*>(s_raw + 46080);

    const int pl = *plast;

    for (int x = tid; x < TT * MAXA / 2; x += 512)
        reinterpret_cast<int*>(idx)[x] = reinterpret_cast<const int*>(g_act_idx)[x];
    if (pl)
        for (int x = tid; x < MAXA * NN / 4; x += 512) cw[x] = 0u;

    const float4 a4 = *reinterpret_cast<const float4*>(g_B + t * NN + i0);
    float p[4] = {a4.x, a4.y, a4.z, a4.w};

    if (pl) {
        __syncthreads();
        const int nm = g_match_cnt[t];
        for (int e = tid; e < nm; e += 512) {
            const unsigned ent = g_match[t * MCAP + e];
            const int js = (int)(ent & 0xFFu);
            const int b2 = (int)((ent >> 8) & 0xFFu) * MAXA;
            const int c2 = (int)(ent >> 16);
            for (int mm = 0; mm < c2; mm++) {
                const unsigned i = (unsigned)(int)idx[b2 + mm];
                const unsigned off = (unsigned)js * NN + i;
                atomicAdd(&cw[off >> 2], 1u << ((off & 3u) * 8u));
            }
        }
        __syncthreads();

        #pragma unroll
        for (int js = 0; js < MAXA; js++) {
            const unsigned w0 = cw[js * (NN / 4) + tid];
            if (w0) {
                const int j = (int)idx[t * MAXA + js];
                #pragma unroll
                for (int c = 0; c < 4; c++) {
                    const unsigned cc = (w0 >> (c * 8)) & 0xFFu;
                    if (cc) {
                        const float v = S[(size_t)(i0 + c) * NN + j];
                        p[c] += fminf(v + LRC * (float)cc, 1.0f) - v;
                    }
                }
            }
        }
    }

    const unsigned mword = g_act_mask[(t + 1) * NW32 + (i0 >> 5)];
    const unsigned nib = (mword >> (i0 & 31)) & 0xFu;
    float pn2 = 0.f, dt = 0.f;
    #pragma unroll
    for (int c = 0; c < 4; c++) {
        pn2 += p[c] * p[c];
        if ((nib >> c) & 1u) dt += p[c];
    }
    #pragma unroll
    for (int o = 16; o; o >>= 1) {
        pn2 += __shfl_xor_sync(0xFFFFFFFFu, pn2, o);
        dt  += __shfl_xor_sync(0xFFFFFFFFu, dt, o);
    }
    __syncthreads();
    if (lane == 0) { red[2 * w] = pn2; red[2 * w + 1] = dt; }
    __syncthreads();
    if (tid == 0) {
        float P2 = 0.f, D = 0.f;
        #pragma unroll
        for (int r = 0; r < 16; r++) { P2 += red[2 * r]; D += red[2 * r + 1]; }
        const float pn = sqrtf(P2);
        float tension;
        if (pl) {
            const float overlap = D / (pn * sqrtf((float)KSEL) + EPSC);
            tension = (pn > 0.0f) ? (1.0f - overlap) : 1.0f;
        } else {
            const float xn = sqrtf((float)g_act_cntfull[t + 1]);
            tension = 1.0f - D / (pn * xn + EPSC);
        }
        out[t] = tension;
    }
}

// ---------------- launch ------------------------------------------------------
extern "C" void kernel_launch(void* const* d_in, const int* in_sizes, int n_in,
                              void* d_out, int out_size) {
    const int*   tokens = (const int*)d_in[0];
    const float* proj   = (const float*)d_in[1];
    const float* sigma  = (const float*)d_in[2];
    const int*   plast  = (const int*)d_in[3];
    float*       out    = (float*)d_out;

    k_topk<<<TT, 512>>>(tokens, proj);
    k_mid<<<NPAN + (TT - 1), 512>>>(sigma, plast);
    k_tension<<<TT - 1, 512>>>(sigma, plast, out);
}